// round 2
// baseline (speedup 1.0000x reference)
#include <cuda_runtime.h>
#include <math.h>

#define NN 2000
#define BB 8
#define LL 12
#define DD 2
#define HH 64
#define EE 16000
#define ETOT 18000
#define NSEQ (NN*BB)                 // 16000
#define OUT1_ELEMS (NSEQ*LL*HH)      // 12,288,000

__device__ float g_out1[OUT1_ELEMS];
__device__ float g_agg[OUT1_ELEMS];

__device__ __forceinline__ float sigf(float x) { return 1.0f / (1.0f + expf(-x)); }

// ---------------------------------------------------------------------------
// GRU1: input D=2, hidden 64. 4 sequences per 256-thread block.
// Thread j (of 64 per sequence) owns hidden unit j.
// smem: WhhT transposed [k=64][g=192] (conflict-free: consecutive g across threads)
// ---------------------------------------------------------------------------
extern "C" __global__ void gru1_kernel(const float* __restrict__ data,
                                       const float* __restrict__ Wih,
                                       const float* __restrict__ Whh,
                                       const float* __restrict__ bih,
                                       const float* __restrict__ bhh,
                                       float* __restrict__ h1_out)
{
    extern __shared__ float sm[];
    float* whhT = sm;              // 64*192 = 12288 floats
    float* h_sh = sm + 64 * 192;   // 4*64

    int tid = threadIdx.x;
    int sub = tid >> 6;
    int j   = tid & 63;
    int s   = blockIdx.x * 4 + sub;

    for (int idx = tid; idx < 192 * 64; idx += 256) {
        int g = idx >> 6, k = idx & 63;
        whhT[k * 192 + g] = Whh[idx];
    }

    // per-thread input weights + biases (D=2)
    float wr0 = Wih[(j)      * 2], wr1 = Wih[(j)      * 2 + 1];
    float wz0 = Wih[(64 + j) * 2], wz1 = Wih[(64 + j) * 2 + 1];
    float wn0 = Wih[(128 + j)* 2], wn1 = Wih[(128 + j)* 2 + 1];
    float br = bih[j], bz = bih[64 + j], bn = bih[128 + j];
    float cr = bhh[j], cz = bhh[64 + j], cn = bhh[128 + j];

    float h = 0.0f;
    h_sh[sub * 64 + j] = 0.0f;
    __syncthreads();

    const float* xp = data + (size_t)s * (LL * DD);
    float* outp = g_out1 + (size_t)s * (LL * HH) + j;

    for (int l = 0; l < LL; l++) {
        float x0 = xp[l * 2], x1 = xp[l * 2 + 1];
        float gir = fmaf(x1, wr1, fmaf(x0, wr0, br));
        float giz = fmaf(x1, wz1, fmaf(x0, wz0, bz));
        float gin = fmaf(x1, wn1, fmaf(x0, wn0, bn));
        float ghr = cr, ghz = cz, ghn = cn;
        const float* hs = h_sh + sub * 64;
        #pragma unroll 8
        for (int k = 0; k < 64; k++) {
            float hk = hs[k];
            const float* wrow = whhT + k * 192 + j;
            ghr = fmaf(hk, wrow[0],   ghr);
            ghz = fmaf(hk, wrow[64],  ghz);
            ghn = fmaf(hk, wrow[128], ghn);
        }
        float r = sigf(gir + ghr);
        float z = sigf(giz + ghz);
        float n = tanhf(fmaf(r, ghn, gin));
        h = fmaf(z, h - n, n);          // (1-z)*n + z*h
        outp[l * HH] = h;
        __syncthreads();                // all k-loop reads done
        h_sh[sub * 64 + j] = h;
        __syncthreads();                // new h visible
    }
    h1_out[s * HH + j] = h;
}

// ---------------------------------------------------------------------------
// zero the aggregation buffer
// ---------------------------------------------------------------------------
extern "C" __global__ void zero_agg_kernel()
{
    for (int i = blockIdx.x * blockDim.x + threadIdx.x; i < OUT1_ELEMS;
         i += gridDim.x * blockDim.x)
        g_agg[i] = 0.0f;
}

// ---------------------------------------------------------------------------
// Edge kernel: one block per edge (incl. self loops).
//  feats -> MLP(16 -> 2) -> per-edge w[128][64] in smem
//  GEMM: [96,128] @ [128,64], leaky_relu, softmax over batch dim (8),
//  msg = alpha * states_j, atomicAdd into g_agg[dst]
// ---------------------------------------------------------------------------
extern "C" __global__ void edge_kernel(const float* __restrict__ features,
                                       const int* __restrict__ ei,
                                       const float* __restrict__ W1,
                                       const float* __restrict__ b1,
                                       const float* __restrict__ W2,
                                       const float* __restrict__ b2,
                                       const float* __restrict__ W3,
                                       const float* __restrict__ b3)
{
    extern __shared__ float sm[];
    float* wsh   = sm;              // 8192  (w[128][64])
    float* sti   = sm + 8192;       // 6144  (states_i [96][64]; reused for alpha)
    float* stj   = sti + 6144;      // 6144  (states_j)
    float* feats = stj + 6144;      // 128
    float* hdn   = feats + 128;     // 16
    float* hdn2  = hdn + 16;        // 2

    int e = blockIdx.x, tid = threadIdx.x;
    int src, dst;
    if (e < EE) { src = ei[e]; dst = ei[EE + e]; }
    else        { src = dst = e - EE; }

    if (tid < 128)
        feats[tid] = (tid < 64) ? features[dst * 64 + tid]
                                : features[src * 64 + (tid - 64)];

    const float* pi = g_out1 + (size_t)dst * 6144;
    const float* pj = g_out1 + (size_t)src * 6144;
    for (int idx = tid; idx < 6144; idx += 256) {
        sti[idx] = pi[idx];
        stj[idx] = pj[idx];
    }
    __syncthreads();

    if (tid < 16) {
        float acc = b1[tid];
        const float* wrow = W1 + tid * 128;
        #pragma unroll 8
        for (int k = 0; k < 128; k++) acc = fmaf(feats[k], wrow[k], acc);
        hdn[tid] = sigf(acc);
    }
    __syncthreads();
    if (tid < 2) {
        float acc = b2[tid];
        const float* wrow = W2 + tid * 16;
        #pragma unroll
        for (int k = 0; k < 16; k++) acc = fmaf(hdn[k], wrow[k], acc);
        hdn2[tid] = sigf(acc);
    }
    __syncthreads();

    float h0 = hdn2[0], h1v = hdn2[1];
    for (int idx = tid; idx < 8192; idx += 256) {
        float2 wv = ((const float2*)W3)[idx];
        wsh[idx] = fmaf(h0, wv.x, fmaf(h1v, wv.y, b3[idx]));
    }
    __syncthreads();

    // GEMM: thread -> col c = tid&63, row group rg = tid>>6; rows rg+4*i (24 rows)
    int c = tid & 63, rg = tid >> 6;
    float acc[24];
    #pragma unroll
    for (int i = 0; i < 24; i++) acc[i] = 0.0f;

    {
        const float* sp = sti + rg * 64;
        for (int k = 0; k < 64; k++) {
            float wv = wsh[k * 64 + c];
            #pragma unroll
            for (int i = 0; i < 24; i++)
                acc[i] = fmaf(sp[i * 256 + k], wv, acc[i]);
        }
    }
    {
        const float* sp = stj + rg * 64;
        for (int k = 0; k < 64; k++) {
            float wv = wsh[(64 + k) * 64 + c];
            #pragma unroll
            for (int i = 0; i < 24; i++)
                acc[i] = fmaf(sp[i * 256 + k], wv, acc[i]);
        }
    }
    __syncthreads();   // everyone done reading sti

    #pragma unroll
    for (int i = 0; i < 24; i++) {
        float v = acc[i];
        v = (v > 0.0f) ? v : 0.01f * v;       // leaky_relu, slope 0.01
        sti[(rg + 4 * i) * 64 + c] = v;       // alpha overwrites sti
    }
    __syncthreads();

    // softmax over batch dim b (8 values per (l,h)), msg, atomic scatter
    float* agg = g_agg + (size_t)dst * 6144;
    for (int p = tid; p < 768; p += 256) {
        int l = p >> 6, hh = p & 63;
        float a[8];
        float m = -1e30f;
        #pragma unroll
        for (int b = 0; b < 8; b++) {
            a[b] = sti[(b * 12 + l) * 64 + hh];
            m = fmaxf(m, a[b]);
        }
        float ssum = 0.0f;
        #pragma unroll
        for (int b = 0; b < 8; b++) { a[b] = expf(a[b] - m); ssum += a[b]; }
        float inv = 1.0f / ssum;
        #pragma unroll
        for (int b = 0; b < 8; b++) {
            int off = (b * 12 + l) * 64 + hh;
            atomicAdd(agg + off, a[b] * inv * stj[off]);
        }
    }
}

// ---------------------------------------------------------------------------
// GRU2: input 64 (relu(agg)), hidden 64. Same layout as GRU1 + x weights.
// ---------------------------------------------------------------------------
extern "C" __global__ void gru2_kernel(const float* __restrict__ Wih,
                                       const float* __restrict__ Whh,
                                       const float* __restrict__ bih,
                                       const float* __restrict__ bhh,
                                       float* __restrict__ h2_out)
{
    extern __shared__ float sm[];
    float* wihT = sm;                 // 12288
    float* whhT = sm + 12288;         // 12288
    float* x_sh = sm + 24576;         // 256
    float* h_sh = sm + 24832;         // 256

    int tid = threadIdx.x;
    int sub = tid >> 6;
    int j   = tid & 63;
    int s   = blockIdx.x * 4 + sub;

    for (int idx = tid; idx < 12288; idx += 256) {
        int g = idx >> 6, k = idx & 63;
        wihT[k * 192 + g] = Wih[idx];
        whhT[k * 192 + g] = Whh[idx];
    }

    float br = bih[j], bz = bih[64 + j], bn = bih[128 + j];
    float cr = bhh[j], cz = bhh[64 + j], cn = bhh[128 + j];

    float h = 0.0f;
    const float* xg = g_agg + (size_t)s * (LL * HH);

    for (int l = 0; l < LL; l++) {
        __syncthreads();              // prior k-loop reads done (also covers weight load)
        x_sh[sub * 64 + j] = fmaxf(xg[l * 64 + j], 0.0f);   // fused relu
        h_sh[sub * 64 + j] = h;
        __syncthreads();

        float gir = br, giz = bz, gin = bn;
        float ghr = cr, ghz = cz, ghn = cn;
        const float* xs = x_sh + sub * 64;
        const float* hs = h_sh + sub * 64;
        #pragma unroll 4
        for (int k = 0; k < 64; k++) {
            float xk = xs[k], hk = hs[k];
            const float* wi = wihT + k * 192 + j;
            const float* wh = whhT + k * 192 + j;
            gir = fmaf(xk, wi[0],   gir);
            giz = fmaf(xk, wi[64],  giz);
            gin = fmaf(xk, wi[128], gin);
            ghr = fmaf(hk, wh[0],   ghr);
            ghz = fmaf(hk, wh[64],  ghz);
            ghn = fmaf(hk, wh[128], ghn);
        }
        float r = sigf(gir + ghr);
        float z = sigf(giz + ghz);
        float n = tanhf(fmaf(r, ghn, gin));
        h = fmaf(z, h - n, n);
    }
    h2_out[s * 64 + j] = h;
}

// ---------------------------------------------------------------------------

static const int GRU1_SMEM = (64 * 192 + 4 * 64) * 4;                 // 50176 B
static const int GRU2_SMEM = (2 * 64 * 192 + 2 * 4 * 64) * 4;        // 100352 B
static const int EDGE_SMEM = (8192 + 6144 + 6144 + 128 + 16 + 2 + 8) * 4;  // ~82.6 KB

extern "C" void kernel_launch(void* const* d_in, const int* in_sizes, int n_in,
                              void* d_out, int out_size)
{
    const float* data     = (const float*)d_in[0];
    const float* features = (const float*)d_in[1];
    const int*   ei       = (const int*)  d_in[2];
    const float* Wih1     = (const float*)d_in[3];
    const float* Whh1     = (const float*)d_in[4];
    const float* bih1     = (const float*)d_in[5];
    const float* bhh1     = (const float*)d_in[6];
    const float* W1       = (const float*)d_in[7];
    const float* b1       = (const float*)d_in[8];
    const float* W2       = (const float*)d_in[9];
    const float* b2       = (const float*)d_in[10];
    const float* W3       = (const float*)d_in[11];
    const float* b3       = (const float*)d_in[12];
    const float* Wih2     = (const float*)d_in[13];
    const float* Whh2     = (const float*)d_in[14];
    const float* bih2     = (const float*)d_in[15];
    const float* bhh2     = (const float*)d_in[16];
    float* out = (float*)d_out;

    cudaFuncSetAttribute(gru1_kernel, cudaFuncAttributeMaxDynamicSharedMemorySize, GRU1_SMEM);
    cudaFuncSetAttribute(gru2_kernel, cudaFuncAttributeMaxDynamicSharedMemorySize, GRU2_SMEM);
    cudaFuncSetAttribute(edge_kernel, cudaFuncAttributeMaxDynamicSharedMemorySize, EDGE_SMEM);

    // h1 at out[0 .. NSEQ*HH), h2 at out[NSEQ*HH .. 2*NSEQ*HH)
    gru1_kernel<<<NSEQ / 4, 256, GRU1_SMEM>>>(data, Wih1, Whh1, bih1, bhh1, out);
    zero_agg_kernel<<<2048, 256>>>();
    edge_kernel<<<ETOT, 256, EDGE_SMEM>>>(features, ei, W1, b1, W2, b2, W3, b3);
    gru2_kernel<<<NSEQ / 4, 256, GRU2_SMEM>>>(Wih2, Whh2, bih2, bhh2, out + NSEQ * HH);
}

// round 3
// speedup vs baseline: 2.1123x; 2.1123x over previous
#include <cuda_runtime.h>
#include <math.h>

#define NN 2000
#define BB 8
#define LL 12
#define DD 2
#define HH 64
#define EE 16000
#define ETOT 18000
#define NSEQ (NN*BB)                 // 16000
#define OUT1_ELEMS (NSEQ*LL*HH)      // 12,288,000

__device__ float g_out1[OUT1_ELEMS];
__device__ float g_agg[OUT1_ELEMS];

// ---------------------------------------------------------------------------
// FMA-only fast math (no MUFU): exp2 via magic-round + poly, rcp via Newton
// ---------------------------------------------------------------------------
__device__ __forceinline__ float fexp2(float y) {
    y = fminf(fmaxf(y, -125.0f), 125.0f);
    float r = __fadd_rn(y, 12582912.0f);            // 1.5*2^23 magic
    int   n = __float_as_int(r) - 0x4B400000;
    float f = __fsub_rn(y, __fsub_rn(r, 12582912.0f));   // f in [-0.5, 0.5]
    float u = f * 0.69314718055994531f;
    float p = fmaf(u, 1.3888889e-3f, 8.3333333e-3f);     // 1/720, 1/120
    p = fmaf(u, p, 4.1666667e-2f);                       // 1/24
    p = fmaf(u, p, 1.6666667e-1f);                       // 1/6
    p = fmaf(u, p, 0.5f);
    p = fmaf(u, p, 1.0f);
    p = fmaf(u, p, 1.0f);
    return p * __int_as_float((n + 127) << 23);
}
__device__ __forceinline__ float frcp(float x) {   // x > 0
    float r = __int_as_float(0x7EF311C3 - __float_as_int(x));
    r = r * __fmaf_rn(-x, r, 2.0f);
    r = r * __fmaf_rn(-x, r, 2.0f);
    r = r * __fmaf_rn(-x, r, 2.0f);
    return r;
}
__device__ __forceinline__ float fsig(float x) {
    return frcp(1.0f + fexp2(-1.4426950408889634f * x));
}
__device__ __forceinline__ float ftanh(float x) {
    float e = fexp2(2.8853900817779268f * x);
    return fmaf(-2.0f, frcp(1.0f + e), 1.0f);
}

// ---------------------------------------------------------------------------
// GRU1: input D=2, hidden 64. 4 thread-groups x 64 threads; each thread owns
// hidden unit j for 4 sequences -> 16 sequences per block.
// Weights transposed in smem, stride 193 (conflict-free store & load).
// h stored transposed [k][4seq] so one LDS.128 feeds 4 sequences.
// ---------------------------------------------------------------------------
extern "C" __global__ void gru1_kernel(const float* __restrict__ data,
                                       const float* __restrict__ Wih,
                                       const float* __restrict__ Whh,
                                       const float* __restrict__ bih,
                                       const float* __restrict__ bhh,
                                       float* __restrict__ h1_out)
{
    extern __shared__ float sm[];
    float* whhT = sm;                      // 64*193 = 12352
    float* h_sh = sm + 12352;              // 4 grp * 64 k * 4 s = 1024
    float* x_sh = sm + 12352 + 1024;       // 16*24 = 384

    const int tid = threadIdx.x;
    const int grp = tid >> 6;
    const int j   = tid & 63;

    for (int idx = tid; idx < 12288; idx += 256) {
        int g = idx >> 6, k = idx & 63;
        int m = g >> 6, jj = g & 63;
        whhT[k * 193 + m * 64 + jj] = Whh[idx];
    }
    for (int idx = tid; idx < 384; idx += 256)
        x_sh[idx] = data[(size_t)blockIdx.x * 384 + idx];

    float wr0 = Wih[j * 2],        wr1 = Wih[j * 2 + 1];
    float wz0 = Wih[(64 + j) * 2], wz1 = Wih[(64 + j) * 2 + 1];
    float wn0 = Wih[(128 + j)* 2], wn1 = Wih[(128 + j)* 2 + 1];
    float br = bih[j], bz = bih[64 + j], bn = bih[128 + j];
    float cr = bhh[j], cz = bhh[64 + j], cn = bhh[128 + j];

    float h[4] = {0.f, 0.f, 0.f, 0.f};
    const int s0 = blockIdx.x * 16 + grp * 4;
    float* outb = g_out1 + (size_t)s0 * 768 + j;   // per-seq stride 768

    for (int l = 0; l < LL; l++) {
        // stage h (transposed)
        *(float4*)&h_sh[grp * 256 + j * 4] = make_float4(h[0], h[1], h[2], h[3]);
        __syncthreads();

        float ghr[4], ghz[4], ghn[4];
        #pragma unroll
        for (int s = 0; s < 4; s++) { ghr[s] = cr; ghz[s] = cz; ghn[s] = cn; }

        const float* wp = whhT + j;
        const float* hp = h_sh + grp * 256;
        #pragma unroll 4
        for (int k = 0; k < 64; k++) {
            float w0 = wp[k * 193];
            float w1 = wp[k * 193 + 64];
            float w2 = wp[k * 193 + 128];
            float4 hv = *(const float4*)&hp[k * 4];
            ghr[0] = fmaf(hv.x, w0, ghr[0]); ghz[0] = fmaf(hv.x, w1, ghz[0]); ghn[0] = fmaf(hv.x, w2, ghn[0]);
            ghr[1] = fmaf(hv.y, w0, ghr[1]); ghz[1] = fmaf(hv.y, w1, ghz[1]); ghn[1] = fmaf(hv.y, w2, ghn[1]);
            ghr[2] = fmaf(hv.z, w0, ghr[2]); ghz[2] = fmaf(hv.z, w1, ghz[2]); ghn[2] = fmaf(hv.z, w2, ghn[2]);
            ghr[3] = fmaf(hv.w, w0, ghr[3]); ghz[3] = fmaf(hv.w, w1, ghz[3]); ghn[3] = fmaf(hv.w, w2, ghn[3]);
        }
        #pragma unroll
        for (int s = 0; s < 4; s++) {
            float x0 = x_sh[(grp * 4 + s) * 24 + l * 2];
            float x1 = x_sh[(grp * 4 + s) * 24 + l * 2 + 1];
            float gir = fmaf(x1, wr1, fmaf(x0, wr0, br));
            float giz = fmaf(x1, wz1, fmaf(x0, wz0, bz));
            float gin = fmaf(x1, wn1, fmaf(x0, wn0, bn));
            float r = fsig(gir + ghr[s]);
            float z = fsig(giz + ghz[s]);
            float n = ftanh(fmaf(r, ghn[s], gin));
            h[s] = fmaf(z, h[s] - n, n);
            outb[s * 768 + l * 64] = h[s];
        }
        __syncthreads();   // all reads of h_sh done before next-store
    }
    #pragma unroll
    for (int s = 0; s < 4; s++)
        h1_out[(s0 + s) * 64 + j] = h[s];
}

// ---------------------------------------------------------------------------
extern "C" __global__ void zero_agg_kernel()
{
    for (int i = blockIdx.x * blockDim.x + threadIdx.x; i < OUT1_ELEMS;
         i += gridDim.x * blockDim.x)
        g_agg[i] = 0.0f;
}

// ---------------------------------------------------------------------------
// Edge kernel: one block per edge. Register-tiled GEMM 96x128x64:
// thread = (tx 0..15 cols*4, ty 0..15 rows*6). 7 LDS + 24 FMA per k.
// FMA-only softmax exp/rcp; vector red.global.add.v4.f32 scatter.
// ---------------------------------------------------------------------------
extern "C" __global__ void edge_kernel(const float* __restrict__ features,
                                       const int* __restrict__ ei,
                                       const float* __restrict__ W1,
                                       const float* __restrict__ b1,
                                       const float* __restrict__ W2,
                                       const float* __restrict__ b2,
                                       const float* __restrict__ W3,
                                       const float* __restrict__ b3)
{
    extern __shared__ float sm[];
    float* wsh   = sm;              // 8192  (w[128][64])
    float* sti   = sm + 8192;       // 6144  (states_i; later alpha)
    float* stj   = sti + 6144;      // 6144  (states_j)
    float* feats = stj + 6144;      // 128
    float* hdn   = feats + 128;     // 16
    float* hdn2  = hdn + 16;        // 2

    const int e = blockIdx.x, tid = threadIdx.x;
    int src, dst;
    if (e < EE) { src = ei[e]; dst = ei[EE + e]; }
    else        { src = dst = e - EE; }

    if (tid < 128)
        feats[tid] = (tid < 64) ? features[dst * 64 + tid]
                                : features[src * 64 + (tid - 64)];

    const float4* pi = (const float4*)(g_out1 + (size_t)dst * 6144);
    const float4* pj = (const float4*)(g_out1 + (size_t)src * 6144);
    for (int idx = tid; idx < 1536; idx += 256) {
        ((float4*)sti)[idx] = pi[idx];
        ((float4*)stj)[idx] = pj[idx];
    }
    __syncthreads();

    if (tid < 16) {
        float acc = b1[tid];
        const float* wrow = W1 + tid * 128;
        #pragma unroll 8
        for (int k = 0; k < 128; k++) acc = fmaf(feats[k], wrow[k], acc);
        hdn[tid] = fsig(acc);
    }
    __syncthreads();
    if (tid < 2) {
        float acc = b2[tid];
        const float* wrow = W2 + tid * 16;
        #pragma unroll
        for (int k = 0; k < 16; k++) acc = fmaf(hdn[k], wrow[k], acc);
        hdn2[tid] = fsig(acc);
    }
    __syncthreads();

    const float h0 = hdn2[0], h1v = hdn2[1];
    for (int idx = tid; idx < 8192; idx += 256) {
        float2 wv = ((const float2*)W3)[idx];
        wsh[idx] = fmaf(h0, wv.x, fmaf(h1v, wv.y, b3[idx]));
    }
    __syncthreads();

    // -------- register-tiled GEMM: rows ty*6..+5, cols tx*4..+3 ----------
    const int tx = tid & 15, ty = tid >> 4;
    float acc[6][4];
    #pragma unroll
    for (int i = 0; i < 6; i++)
        #pragma unroll
        for (int c = 0; c < 4; c++) acc[i][c] = 0.0f;

    const float* s0 = sti + (ty * 6) * 64;
    const float* s1 = stj + (ty * 6) * 64;
    const float* wp0 = wsh + tx * 4;

    #pragma unroll 2
    for (int k = 0; k < 64; k++) {
        float4 w = *(const float4*)(wp0 + k * 64);
        #pragma unroll
        for (int i = 0; i < 6; i++) {
            float s = s0[i * 64 + k];
            acc[i][0] = fmaf(s, w.x, acc[i][0]);
            acc[i][1] = fmaf(s, w.y, acc[i][1]);
            acc[i][2] = fmaf(s, w.z, acc[i][2]);
            acc[i][3] = fmaf(s, w.w, acc[i][3]);
        }
    }
    #pragma unroll 2
    for (int k = 0; k < 64; k++) {
        float4 w = *(const float4*)(wp0 + (64 + k) * 64);
        #pragma unroll
        for (int i = 0; i < 6; i++) {
            float s = s1[i * 64 + k];
            acc[i][0] = fmaf(s, w.x, acc[i][0]);
            acc[i][1] = fmaf(s, w.y, acc[i][1]);
            acc[i][2] = fmaf(s, w.z, acc[i][2]);
            acc[i][3] = fmaf(s, w.w, acc[i][3]);
        }
    }
    __syncthreads();   // all sti reads done

    #pragma unroll
    for (int i = 0; i < 6; i++) {
        float4 v;
        v.x = acc[i][0] > 0.f ? acc[i][0] : 0.01f * acc[i][0];
        v.y = acc[i][1] > 0.f ? acc[i][1] : 0.01f * acc[i][1];
        v.z = acc[i][2] > 0.f ? acc[i][2] : 0.01f * acc[i][2];
        v.w = acc[i][3] > 0.f ? acc[i][3] : 0.01f * acc[i][3];
        *(float4*)&sti[(ty * 6 + i) * 64 + tx * 4] = v;   // alpha
    }
    __syncthreads();

    // -------- softmax over batch (8) + msg + vector atomic scatter -------
    if (tid < 192) {
        const int l = tid >> 4, h4 = tid & 15;
        float4 a[8];
        float4 m = make_float4(-1e30f, -1e30f, -1e30f, -1e30f);
        #pragma unroll
        for (int b = 0; b < 8; b++) {
            a[b] = *(const float4*)&sti[((b * 12 + l) * 64) + h4 * 4];
            m.x = fmaxf(m.x, a[b].x); m.y = fmaxf(m.y, a[b].y);
            m.z = fmaxf(m.z, a[b].z); m.w = fmaxf(m.w, a[b].w);
        }
        float4 ssum = make_float4(0.f, 0.f, 0.f, 0.f);
        #pragma unroll
        for (int b = 0; b < 8; b++) {
            a[b].x = fexp2(1.4426950408889634f * (a[b].x - m.x));
            a[b].y = fexp2(1.4426950408889634f * (a[b].y - m.y));
            a[b].z = fexp2(1.4426950408889634f * (a[b].z - m.z));
            a[b].w = fexp2(1.4426950408889634f * (a[b].w - m.w));
            ssum.x += a[b].x; ssum.y += a[b].y; ssum.z += a[b].z; ssum.w += a[b].w;
        }
        float4 inv = make_float4(frcp(ssum.x), frcp(ssum.y), frcp(ssum.z), frcp(ssum.w));
        float* aggb = g_agg + (size_t)dst * 6144;
        #pragma unroll
        for (int b = 0; b < 8; b++) {
            int off = (b * 12 + l) * 64 + h4 * 4;
            float4 sj = *(const float4*)&stj[off];
            float4 msg;
            msg.x = a[b].x * inv.x * sj.x;
            msg.y = a[b].y * inv.y * sj.y;
            msg.z = a[b].z * inv.z * sj.z;
            msg.w = a[b].w * inv.w * sj.w;
            asm volatile("red.global.add.v4.f32 [%0], {%1,%2,%3,%4};"
                         :: "l"(aggb + off), "f"(msg.x), "f"(msg.y),
                            "f"(msg.z), "f"(msg.w) : "memory");
        }
    }
}

// ---------------------------------------------------------------------------
// GRU2: input 64 (relu(agg)), hidden 64. 4 seqs/thread, 16 seqs/block.
// Combined weights transposed in smem, stride 385 (conflict-free).
// ---------------------------------------------------------------------------
extern "C" __global__ void gru2_kernel(const float* __restrict__ Wih,
                                       const float* __restrict__ Whh,
                                       const float* __restrict__ bih,
                                       const float* __restrict__ bhh,
                                       float* __restrict__ h2_out)
{
    extern __shared__ float sm[];
    float* wT   = sm;                     // 64*385 = 24640
    float* h_sh = sm + 24640;             // 1024
    float* x_sh = sm + 24640 + 1024;      // 1024

    const int tid = threadIdx.x;
    const int grp = tid >> 6;
    const int j   = tid & 63;

    for (int idx = tid; idx < 12288; idx += 256) {
        int g = idx >> 6, k = idx & 63;
        int m = g >> 6, jj = g & 63;
        wT[k * 385 + m * 64 + jj]       = Wih[idx];
        wT[k * 385 + 192 + m * 64 + jj] = Whh[idx];
    }

    float br = bih[j], bz = bih[64 + j], bn = bih[128 + j];
    float cr = bhh[j], cz = bhh[64 + j], cn = bhh[128 + j];

    float h[4] = {0.f, 0.f, 0.f, 0.f};
    const int s0 = blockIdx.x * 16 + grp * 4;
    const float* xg = g_agg + (size_t)s0 * 768 + j;

    for (int l = 0; l < LL; l++) {
        float4 xv;
        xv.x = fmaxf(xg[0 * 768 + l * 64], 0.0f);
        xv.y = fmaxf(xg[1 * 768 + l * 64], 0.0f);
        xv.z = fmaxf(xg[2 * 768 + l * 64], 0.0f);
        xv.w = fmaxf(xg[3 * 768 + l * 64], 0.0f);
        *(float4*)&x_sh[grp * 256 + j * 4] = xv;
        *(float4*)&h_sh[grp * 256 + j * 4] = make_float4(h[0], h[1], h[2], h[3]);
        __syncthreads();

        float gr[4], gz[4], gn[4];
        #pragma unroll
        for (int s = 0; s < 4; s++) { gr[s] = br + cr; gz[s] = bz + cz; gn[s] = bn; }
        float ghn[4] = {cn, cn, cn, cn};

        const float* wp = wT + j;
        const float* hp = h_sh + grp * 256;
        const float* xp = x_sh + grp * 256;
        #pragma unroll 2
        for (int k = 0; k < 64; k++) {
            float wi0 = wp[k * 385];
            float wi1 = wp[k * 385 + 64];
            float wi2 = wp[k * 385 + 128];
            float wh0 = wp[k * 385 + 192];
            float wh1 = wp[k * 385 + 256];
            float wh2 = wp[k * 385 + 320];
            float4 xk = *(const float4*)&xp[k * 4];
            float4 hk = *(const float4*)&hp[k * 4];
            gr[0] = fmaf(xk.x, wi0, gr[0]); gz[0] = fmaf(xk.x, wi1, gz[0]); gn[0] = fmaf(xk.x, wi2, gn[0]);
            gr[0] = fmaf(hk.x, wh0, gr[0]); gz[0] = fmaf(hk.x, wh1, gz[0]); ghn[0] = fmaf(hk.x, wh2, ghn[0]);
            gr[1] = fmaf(xk.y, wi0, gr[1]); gz[1] = fmaf(xk.y, wi1, gz[1]); gn[1] = fmaf(xk.y, wi2, gn[1]);
            gr[1] = fmaf(hk.y, wh0, gr[1]); gz[1] = fmaf(hk.y, wh1, gz[1]); ghn[1] = fmaf(hk.y, wh2, ghn[1]);
            gr[2] = fmaf(xk.z, wi0, gr[2]); gz[2] = fmaf(xk.z, wi1, gz[2]); gn[2] = fmaf(xk.z, wi2, gn[2]);
            gr[2] = fmaf(hk.z, wh0, gr[2]); gz[2] = fmaf(hk.z, wh1, gz[2]); ghn[2] = fmaf(hk.z, wh2, ghn[2]);
            gr[3] = fmaf(xk.w, wi0, gr[3]); gz[3] = fmaf(xk.w, wi1, gz[3]); gn[3] = fmaf(xk.w, wi2, gn[3]);
            gr[3] = fmaf(hk.w, wh0, gr[3]); gz[3] = fmaf(hk.w, wh1, gz[3]); ghn[3] = fmaf(hk.w, wh2, ghn[3]);
        }
        #pragma unroll
        for (int s = 0; s < 4; s++) {
            float r = fsig(gr[s]);
            float z = fsig(gz[s]);
            float n = ftanh(fmaf(r, ghn[s], gn[s]));
            h[s] = fmaf(z, h[s] - n, n);
        }
        __syncthreads();
    }
    #pragma unroll
    for (int s = 0; s < 4; s++)
        h2_out[(s0 + s) * 64 + j] = h[s];
}

// ---------------------------------------------------------------------------

static const int GRU1_SMEM = (12352 + 1024 + 384) * 4;          // ~55 KB
static const int GRU2_SMEM = (24640 + 1024 + 1024) * 4;         // ~107 KB
static const int EDGE_SMEM = (8192 + 6144 + 6144 + 128 + 16 + 2 + 8) * 4;  // ~82.6 KB

extern "C" void kernel_launch(void* const* d_in, const int* in_sizes, int n_in,
                              void* d_out, int out_size)
{
    const float* data     = (const float*)d_in[0];
    const float* features = (const float*)d_in[1];
    const int*   ei       = (const int*)  d_in[2];
    const float* Wih1     = (const float*)d_in[3];
    const float* Whh1     = (const float*)d_in[4];
    const float* bih1     = (const float*)d_in[5];
    const float* bhh1     = (const float*)d_in[6];
    const float* W1       = (const float*)d_in[7];
    const float* b1       = (const float*)d_in[8];
    const float* W2       = (const float*)d_in[9];
    const float* b2       = (const float*)d_in[10];
    const float* W3       = (const float*)d_in[11];
    const float* b3       = (const float*)d_in[12];
    const float* Wih2     = (const float*)d_in[13];
    const float* Whh2     = (const float*)d_in[14];
    const float* bih2     = (const float*)d_in[15];
    const float* bhh2     = (const float*)d_in[16];
    float* out = (float*)d_out;

    cudaFuncSetAttribute(gru1_kernel, cudaFuncAttributeMaxDynamicSharedMemorySize, GRU1_SMEM);
    cudaFuncSetAttribute(gru2_kernel, cudaFuncAttributeMaxDynamicSharedMemorySize, GRU2_SMEM);
    cudaFuncSetAttribute(edge_kernel, cudaFuncAttributeMaxDynamicSharedMemorySize, EDGE_SMEM);

    gru1_kernel<<<NSEQ / 16, 256, GRU1_SMEM>>>(data, Wih1, Whh1, bih1, bhh1, out);
    zero_agg_kernel<<<2048, 256>>>();
    edge_kernel<<<ETOT, 256, EDGE_SMEM>>>(features, ei, W1, b1, W2, b2, W3, b3);
    gru2_kernel<<<NSEQ / 16, 256, GRU2_SMEM>>>(Wih2, Whh2, bih2, bhh2, out + NSEQ * HH);
}